// round 15
// baseline (speedup 1.0000x reference)
#include <cuda_runtime.h>
#include <math.h>

#define Nn 10000
#define Ee 320000
#define KTOT 644     // 576 scalar cat + 68 vn
#define KPAD 656     // 41 * 16
#define OUTC 352     // 256 scalar + 96 vector

typedef unsigned long long u64;

// ---------------- f32x2 / misc helpers ----------------
__device__ __forceinline__ u64 pk2(float x, float y) {
    u64 r; asm("mov.b64 %0,{%1,%2};" : "=l"(r) : "f"(x), "f"(y)); return r;
}
__device__ __forceinline__ void upk2(u64 v, float& x, float& y) {
    asm("mov.b64 {%0,%1},%2;" : "=f"(x), "=f"(y) : "l"(v));
}
__device__ __forceinline__ u64 fma2(u64 a, u64 b, u64 c) {
    u64 r; asm("fma.rn.f32x2 %0,%1,%2,%3;" : "=l"(r) : "l"(a), "l"(b), "l"(c)); return r;
}
__device__ __forceinline__ u64 add2(u64 a, u64 b) {
    u64 r; asm("add.rn.f32x2 %0,%1,%2;" : "=l"(r) : "l"(a), "l"(b)); return r;
}
__device__ __forceinline__ float sqrt_apx(float x) {
    float r; asm("sqrt.approx.f32 %0,%1;" : "=f"(r) : "f"(x)); return r;
}
// channel -> permuted slot within a 68-float nvh row: pairs (h, h+32) adjacent
__device__ __forceinline__ int perm68(int h) {
    return h < 32 ? 2 * h : (h < 64 ? 2 * (h - 32) + 1 : h);
}

// ---------------- scratch (zero-initialized at module load) ----------------
__device__ int   g_cnt[Nn];
__device__ int   g_off[Nn + 1];
__device__ int   g_cur[Nn];
__device__ int   g_order[Ee];
__device__ float g_nvh[(size_t)Nn * 408];   // [n][j][68-permuted], j=0..2 src-d, 3..5 dst-d
__device__ float g_agg[(size_t)Nn * KPAD];  // GEMM X row
__device__ float g_vagg[(size_t)Nn * 112];  // [0,96) Σv_src | [96,108) Σe_v
__device__ float g_M[68 * 32];              // wh @ wv

// ---------------- K1: histogram of dst (g_cnt zeroed by k_sum at end of each run) ----------------
__global__ void k_hist(const int* __restrict__ ei) {
    int e = blockIdx.x * blockDim.x + threadIdx.x;
    if (e < Ee) atomicAdd(&g_cnt[ei[Ee + e]], 1);
}

// ---------------- K2: block0 = exclusive scan, block1 = M = wh@wv ----------------
__global__ void k_scan_mw(const float* __restrict__ wh, const float* __restrict__ wv) {
    if (blockIdx.x == 1) {
        for (int t = threadIdx.x; t < 68 * 32; t += 1024) {
            int c = t >> 5, o = t & 31;
            float s = 0.f;
#pragma unroll 4
            for (int h = 0; h < 68; h++) s = fmaf(wh[c * 68 + h], wv[h * 32 + o], s);
            g_M[t] = s;
        }
        return;
    }
    __shared__ int sm[1024];
    int t = threadIdx.x;
    int base = t * 10;
    int loc[10];
    int s = 0;
#pragma unroll
    for (int j = 0; j < 10; j++) {
        int idx = base + j;
        int v = (idx < Nn) ? g_cnt[idx] : 0;
        loc[j] = v; s += v;
    }
    sm[t] = s;
    __syncthreads();
    for (int o = 1; o < 1024; o <<= 1) {
        int v = (t >= o) ? sm[t - o] : 0;
        __syncthreads();
        sm[t] += v;
        __syncthreads();
    }
    int run = sm[t] - s;
#pragma unroll
    for (int j = 0; j < 10; j++) {
        int idx = base + j;
        if (idx < Nn) { g_off[idx] = run; g_cur[idx] = run; run += loc[j]; }
    }
    if (t == 1023) g_off[Nn] = sm[1023];
}

// ---------------- K3: scatter edge ids ----------------
__global__ void k_scatter(const int* __restrict__ ei) {
    int e = blockIdx.x * blockDim.x + threadIdx.x;
    if (e < Ee) {
        int d = ei[Ee + e];
        int pos = atomicAdd(&g_cur[d], 1);
        g_order[pos] = e;
    }
}

// ---------------- K4: per-node vector projections, f32x2 node-pairs, 16 nodes/block ----------------
__global__ void __launch_bounds__(224)
k_nvh(const float* __restrict__ node_v, const float* __restrict__ wh) {
    __shared__ float swh[68 * 68];               // 18.5 KB
    __shared__ __align__(8) float svp[3 * 512];  // [d][c][q], q contiguous (16), 6 KB
    int t = threadIdx.x;                         // 224 threads
    int n0 = blockIdx.x * 16;
    for (int i = t; i < 68 * 68; i += 224) swh[i] = wh[i];
    for (int i = t; i < 16 * 96; i += 224) {
        int q = i / 96, c96 = i - q * 96;        // c96 = c*3 + d
        int c = c96 / 3, d = c96 - c * 3;
        svp[d * 512 + c * 16 + q] = node_v[(size_t)(n0 + q) * 96 + c96];
    }
    __syncthreads();
    if (t < 204) {
        int d = t / 68, h = t - d * 68;
        int ps = perm68(h);
        const float* sv = &svp[d * 512];
        u64 fs[8], fd[8];
#pragma unroll
        for (int p = 0; p < 8; p++) { fs[p] = 0; fd[p] = 0; }
#pragma unroll 4
        for (int c = 0; c < 32; c++) {
            float ws = swh[c * 68 + h], wd = swh[(36 + c) * 68 + h];
            u64 ws2 = pk2(ws, ws), wd2 = pk2(wd, wd);
#pragma unroll
            for (int p = 0; p < 8; p++) {
                u64 a = *(const u64*)(sv + c * 16 + 2 * p);   // node pair (2p, 2p+1)
                fs[p] = fma2(a, ws2, fs[p]);
                fd[p] = fma2(a, wd2, fd[p]);
            }
        }
#pragma unroll
        for (int p = 0; p < 8; p++) {
            float s0, s1, d0, d1;
            upk2(fs[p], s0, s1);
            upk2(fd[p], d0, d1);
            size_t b0 = (size_t)(n0 + 2 * p) * 408;
            size_t b1 = (size_t)(n0 + 2 * p + 1) * 408;
            g_nvh[b0 + d * 68 + ps] = s0;
            g_nvh[b1 + d * 68 + ps] = s1;
            g_nvh[b0 + (3 + d) * 68 + ps] = d0;
            g_nvh[b1 + (3 + d) * 68 + ps] = d1;
        }
    }
}

// ---------------- K5: streaming sums, one warp per node (lean: no norm state) ----------------
__global__ void k_sum(const float* __restrict__ node_s, const float* __restrict__ node_v,
                      const float* __restrict__ edge_s, const float* __restrict__ edge_v,
                      const int* __restrict__ ei) {
    int warp = (blockIdx.x * blockDim.x + threadIdx.x) >> 5;
    int lane = threadIdx.x & 31;
    if (warp >= Nn) return;
    int n = warp;
    bool l24 = (lane < 24), l12 = (lane < 12);

    u64 aS0 = 0, aS1 = 0, aS2 = 0, aS3 = 0;
    u64 aE = 0;
    u64 aV0 = 0, aV1 = 0;
    float aEV = 0.f;

    int p0 = g_off[n], p1 = g_off[n + 1];
    int m = p1 - p0;
    if (m > 0) {
        int e = g_order[p0];
        int s = ei[e];
        for (int p = p0; p < p1; p++) {
            int e_nx = e, s_nx = s;
            if (p + 1 < p1) { e_nx = g_order[p + 1]; s_nx = ei[e_nx]; }

            {
                const ulonglong2* a = (const ulonglong2*)(node_s + (size_t)s * 256 + 4 * lane);
                const ulonglong2* b = (const ulonglong2*)(node_s + (size_t)s * 256 + 128 + 4 * lane);
                ulonglong2 x = *a, y = *b;
                aS0 = add2(aS0, x.x); aS1 = add2(aS1, x.y);
                aS2 = add2(aS2, y.x); aS3 = add2(aS3, y.y);
            }
            aE = add2(aE, *(const u64*)(edge_s + (size_t)e * 64 + 2 * lane));
            if (l24) {
                ulonglong2 v = *(const ulonglong2*)(node_v + (size_t)s * 96 + 4 * lane);
                aV0 = add2(aV0, v.x); aV1 = add2(aV1, v.y);
            }
            if (l12) aEV += edge_v[(size_t)e * 12 + lane];

            e = e_nx; s = s_nx;
        }
    }

    float cnt = (float)m;
    float* ag = g_agg + (size_t)n * KPAD;
    *(ulonglong2*)(ag + 4 * lane)       = make_ulonglong2(aS0, aS1);
    *(ulonglong2*)(ag + 128 + 4 * lane) = make_ulonglong2(aS2, aS3);
    *(u64*)(ag + 256 + 2 * lane) = aE;
    {   // cnt * node_s[n]
        float4 a = *(const float4*)(node_s + (size_t)n * 256 + 4 * lane);
        float4 b = *(const float4*)(node_s + (size_t)n * 256 + 128 + 4 * lane);
        a.x *= cnt; a.y *= cnt; a.z *= cnt; a.w *= cnt;
        b.x *= cnt; b.y *= cnt; b.z *= cnt; b.w *= cnt;
        *(float4*)(ag + 320 + 4 * lane) = a;
        *(float4*)(ag + 448 + 4 * lane) = b;
    }

    float* vg = g_vagg + (size_t)n * 112;
    if (l24) *(ulonglong2*)(vg + 4 * lane) = make_ulonglong2(aV0, aV1);
    if (l12) vg[96 + lane] = aEV;

    if (lane == 0) g_cnt[n] = 0;          // reset histogram for next replay
}

// ---------------- K6: vn norms, one warp per node (lean: no sum state) ----------------
__global__ void k_norm(const float* __restrict__ edge_v, const float* __restrict__ wh,
                       const int* __restrict__ ei) {
    int warp = (blockIdx.x * blockDim.x + threadIdx.x) >> 5;
    int lane = threadIdx.x & 31;
    if (warp >= Nn) return;
    int n = warp;
    int h0 = lane, h1 = lane + 32;
    int lcl = (lane < 4) ? lane : 0;       // clamped k2 lane
    int h2s = 64 + lcl;                    // permuted slot for k2 channels
    bool h2v = (lane < 4);

    // per-node constants: k0,k1 packed via LDG.64 on permuted rows, k2 scalar
    u64 nd01[3], we01[4];
    float nd2[3], we2[4];
#pragma unroll
    for (int d = 0; d < 3; d++) {
        const float* p = g_nvh + (size_t)n * 408 + (3 + d) * 68;
        nd01[d] = *(const u64*)(p + 2 * lane);
        nd2[d]  = p[h2s];
    }
#pragma unroll
    for (int c = 0; c < 4; c++) {
        const float* p = wh + (32 + c) * 68;
        we01[c] = pk2(p[h0], p[h1]);
        we2[c]  = p[64 + lcl];
    }

    u64 aN01 = 0;
    float aN2 = 0.f;

    int p0 = g_off[n], p1 = g_off[n + 1];
    if (p0 < p1) {
        int e = g_order[p0];
        int s = ei[e];
        for (int p = p0; p < p1; p++) {
            int e_nx = e, s_nx = s;
            if (p + 1 < p1) { e_nx = g_order[p + 1]; s_nx = ei[e_nx]; }

            // edge_v broadcast: [c][d] layout, 12 floats
            const float4* evp = (const float4*)(edge_v + (size_t)e * 12);
            float4 q0 = evp[0], q1 = evp[1], q2 = evp[2];

            const float* nh = g_nvh + (size_t)s * 408;
            u64 ssq01 = 0;
            float ssq2 = 0.f;
#pragma unroll
            for (int d = 0; d < 3; d++) {
                u64 nv2 = *(const u64*)(nh + d * 68 + 2 * lane);
                float nc = nh[d * 68 + h2s];
                u64 v2 = add2(nv2, nd01[d]);
                float vs = nc + nd2[d];
                float c0 = (d == 0) ? q0.x : (d == 1) ? q0.y : q0.z;
                float c1 = (d == 0) ? q0.w : (d == 1) ? q1.x : q1.y;
                float c2 = (d == 0) ? q1.z : (d == 1) ? q1.w : q2.x;
                float c3 = (d == 0) ? q2.y : (d == 1) ? q2.z : q2.w;
                v2 = fma2(pk2(c0, c0), we01[0], v2);
                v2 = fma2(pk2(c1, c1), we01[1], v2);
                v2 = fma2(pk2(c2, c2), we01[2], v2);
                v2 = fma2(pk2(c3, c3), we01[3], v2);
                vs = fmaf(c0, we2[0], vs);
                vs = fmaf(c1, we2[1], vs);
                vs = fmaf(c2, we2[2], vs);
                vs = fmaf(c3, we2[3], vs);
                ssq01 = fma2(v2, v2, ssq01);
                ssq2 = fmaf(vs, vs, ssq2);
            }
            float s0, s1;
            upk2(ssq01, s0, s1);
            aN01 = add2(aN01, pk2(sqrt_apx(fmaxf(s0, 1e-8f)), sqrt_apx(fmaxf(s1, 1e-8f))));
            aN2 += sqrt_apx(fmaxf(ssq2, 1e-8f));

            e = e_nx; s = s_nx;
        }
    }

    float* ag = g_agg + (size_t)n * KPAD;
    {
        float n0v, n1v;
        upk2(aN01, n0v, n1v);
        ag[576 + lane] = n0v; ag[608 + lane] = n1v;
    }
    if (h2v) ag[640 + lane] = aN2;
    if (lane >= 4 && lane < 16) ag[640 + lane] = 0.f;   // pad [644,656)
}

// ---------------- K7: node GEMM, double-buffered, FFMA2, 139 balanced blocks ----------------
__global__ void __launch_bounds__(256, 1)
k_gemm(const float* __restrict__ ws_w, const float* __restrict__ ws_b,
       float* __restrict__ out) {
    __shared__ float Xs[2][16][72];
    __shared__ float Ws[2][16][256];
    __shared__ float sCnt[72];
    int tid = threadIdx.x;
    int r0 = blockIdx.x * 72;
    int tc = tid & 63;
    int rg = tid >> 6;

    if (tid < 72) {
        int r = r0 + tid;
        sCnt[tid] = (r < Nn) ? (float)(g_off[r + 1] - g_off[r]) : 0.f;
    }

    int rowA = tid >> 2, kqA = tid & 3;
    int rA = r0 + rowA;
    int rowB = (tid + 256) >> 2, kqB = tid & 3;
    int rB = r0 + rowB;

    float4 x0, x1, w[4];
    const float4 z4 = make_float4(0.f, 0.f, 0.f, 0.f);

    auto loadTiles = [&](int kt) {
        int k0 = kt * 16;
        x0 = (rA < Nn) ? *(const float4*)(g_agg + (size_t)rA * KPAD + k0 + kqA * 4) : z4;
        if (tid < 32)
            x1 = (rB < Nn) ? *(const float4*)(g_agg + (size_t)rB * KPAD + k0 + kqB * 4) : z4;
#pragma unroll
        for (int q = 0; q < 4; q++) {
            int f = tid + 256 * q;
            int kk = f >> 6, c4 = (f & 63) * 4;
            int k = k0 + kk;
            w[q] = (k < KTOT) ? *(const float4*)(ws_w + (size_t)k * 256 + c4) : z4;
        }
    };
    auto stsTiles = [&](int b) {
        Xs[b][kqA * 4 + 0][rowA] = x0.x;
        Xs[b][kqA * 4 + 1][rowA] = x0.y;
        Xs[b][kqA * 4 + 2][rowA] = x0.z;
        Xs[b][kqA * 4 + 3][rowA] = x0.w;
        if (tid < 32) {
            Xs[b][kqB * 4 + 0][rowB] = x1.x;
            Xs[b][kqB * 4 + 1][rowB] = x1.y;
            Xs[b][kqB * 4 + 2][rowB] = x1.z;
            Xs[b][kqB * 4 + 3][rowB] = x1.w;
        }
#pragma unroll
        for (int q = 0; q < 4; q++) {
            int f = tid + 256 * q;
            int kk = f >> 6, c4 = (f & 63) * 4;
            *(float4*)(&Ws[b][kk][c4]) = w[q];
        }
    };

    u64 acc[9][4];
#pragma unroll
    for (int p = 0; p < 9; p++)
#pragma unroll
        for (int c = 0; c < 4; c++) acc[p][c] = 0;

    loadTiles(0);
    stsTiles(0);
    __syncthreads();

    for (int kt = 0; kt < 41; kt++) {
        int cur = kt & 1;
        if (kt < 40) loadTiles(kt + 1);
#pragma unroll
        for (int kk = 0; kk < 16; kk++) {
            float4 b4 = *(const float4*)(&Ws[cur][kk][tc * 4]);
            u64 b0 = pk2(b4.x, b4.x), b1 = pk2(b4.y, b4.y);
            u64 b2 = pk2(b4.z, b4.z), b3 = pk2(b4.w, b4.w);
#pragma unroll
            for (int p = 0; p < 9; p++) {
                u64 av = *(const u64*)(&Xs[cur][kk][rg * 18 + 2 * p]);
                acc[p][0] = fma2(av, b0, acc[p][0]);
                acc[p][1] = fma2(av, b1, acc[p][1]);
                acc[p][2] = fma2(av, b2, acc[p][2]);
                acc[p][3] = fma2(av, b3, acc[p][3]);
            }
        }
        if (kt < 40) stsTiles(cur ^ 1);
        __syncthreads();
    }

    float4 bias = *(const float4*)(ws_b + tc * 4);
#pragma unroll
    for (int p = 0; p < 9; p++) {
        int row = rg * 18 + 2 * p;
        float lo[4], hi[4];
#pragma unroll
        for (int c = 0; c < 4; c++) upk2(acc[p][c], lo[c], hi[c]);
#pragma unroll
        for (int h = 0; h < 2; h++) {
            int r = r0 + row + h;
            if (r >= Nn) continue;
            float cnt = sCnt[row + h];
            float sc = 1.f / fmaxf(cnt, 1.f);
            float bc = (cnt > 0.f) ? 1.f : 0.f;
            const float* v = h ? hi : lo;
            float4 o;
            o.x = v[0] * sc + bias.x * bc;
            o.y = v[1] * sc + bias.y * bc;
            o.z = v[2] * sc + bias.z * bc;
            o.w = v[3] * sc + bias.w * bc;
            *(float4*)(out + (size_t)r * OUTC + tc * 4) = o;
        }
    }
}

// ---------------- K8: vector output ----------------
__global__ void k_vec(const float* __restrict__ node_v, float* __restrict__ out) {
    __shared__ float Msm[68 * 32];
    __shared__ float vag[204];
    int t = threadIdx.x;                   // 96 threads
    for (int i = t; i < 68 * 32; i += 96) Msm[i] = g_M[i];
#pragma unroll 1
    for (int q = 0; q < 8; q++) {
        int n = blockIdx.x * 8 + q;        // grid = 1250
        float cf = (float)(g_off[n + 1] - g_off[n]);
        __syncthreads();
        vag[t] = g_vagg[(size_t)n * 112 + t];
        if (t < 12) vag[96 + t] = g_vagg[(size_t)n * 112 + 96 + t];
        vag[108 + t] = cf * node_v[(size_t)n * 96 + t];
        __syncthreads();
        int o = t / 3, d = t % 3;
        float s = 0.f;
#pragma unroll 4
        for (int c = 0; c < 68; c++) s = fmaf(vag[c * 3 + d], Msm[c * 32 + o], s);
        out[(size_t)n * OUTC + 256 + o * 3 + d] = s / fmaxf(cf, 1.f);
    }
}

// ---------------- launch ----------------
extern "C" void kernel_launch(void* const* d_in, const int* in_sizes, int n_in,
                              void* d_out, int out_size) {
    const float* node_s = (const float*)d_in[0];
    const float* node_v = (const float*)d_in[1];
    const float* edge_s = (const float*)d_in[2];
    const float* edge_v = (const float*)d_in[3];
    const float* wh     = (const float*)d_in[4];
    const float* ws_w   = (const float*)d_in[5];
    const float* ws_b   = (const float*)d_in[6];
    const float* wv     = (const float*)d_in[7];
    const int*   ei     = (const int*)d_in[8];
    float* out = (float*)d_out;

    k_hist<<<(Ee + 255) / 256, 256>>>(ei);
    k_scan_mw<<<2, 1024>>>(wh, wv);
    k_scatter<<<(Ee + 255) / 256, 256>>>(ei);
    k_nvh<<<Nn / 16, 224>>>(node_v, wh);
    k_sum<<<(Nn + 7) / 8, 256>>>(node_s, node_v, edge_s, edge_v, ei);
    k_norm<<<(Nn + 7) / 8, 256>>>(edge_v, wh, ei);
    k_gemm<<<139, 256>>>(ws_w, ws_b, out);
    k_vec<<<Nn / 8, 96>>>(node_v, out);
}

// round 16
// speedup vs baseline: 1.0858x; 1.0858x over previous
#include <cuda_runtime.h>
#include <math.h>

#define Nn 10000
#define Ee 320000
#define KTOT 644     // 576 scalar cat + 68 vn
#define KPAD 656     // 41 * 16
#define OUTC 352     // 256 scalar + 96 vector

typedef unsigned long long u64;

// ---------------- f32x2 / misc helpers ----------------
__device__ __forceinline__ u64 pk2(float x, float y) {
    u64 r; asm("mov.b64 %0,{%1,%2};" : "=l"(r) : "f"(x), "f"(y)); return r;
}
__device__ __forceinline__ void upk2(u64 v, float& x, float& y) {
    asm("mov.b64 {%0,%1},%2;" : "=f"(x), "=f"(y) : "l"(v));
}
__device__ __forceinline__ u64 fma2(u64 a, u64 b, u64 c) {
    u64 r; asm("fma.rn.f32x2 %0,%1,%2,%3;" : "=l"(r) : "l"(a), "l"(b), "l"(c)); return r;
}
__device__ __forceinline__ u64 add2(u64 a, u64 b) {
    u64 r; asm("add.rn.f32x2 %0,%1,%2;" : "=l"(r) : "l"(a), "l"(b)); return r;
}
__device__ __forceinline__ float sqrt_apx(float x) {
    float r; asm("sqrt.approx.f32 %0,%1;" : "=f"(r) : "f"(x)); return r;
}
// channel -> permuted slot within a 68-float nvh row: pairs (h, h+32) adjacent
__device__ __forceinline__ int perm68(int h) {
    return h < 32 ? 2 * h : (h < 64 ? 2 * (h - 32) + 1 : h);
}

// ---------------- scratch (zero-initialized at module load) ----------------
__device__ int   g_cnt[Nn];
__device__ int   g_off[Nn + 1];
__device__ int   g_cur[Nn];
__device__ int   g_order[Ee];
__device__ float g_nvh[(size_t)Nn * 408];   // [n][j][68-permuted], j=0..2 src-d, 3..5 dst-d
__device__ float g_agg[(size_t)Nn * KPAD];  // GEMM X row
__device__ float g_vagg[(size_t)Nn * 112];  // [0,96) Σv_src | [96,108) Σe_v
__device__ float g_M[68 * 32];              // wh @ wv

// ---------------- K1: histogram of dst (g_cnt zeroed by k_agg at end of each run) ----------------
__global__ void k_hist(const int* __restrict__ ei) {
    int e = blockIdx.x * blockDim.x + threadIdx.x;
    if (e < Ee) atomicAdd(&g_cnt[ei[Ee + e]], 1);
}

// ---------------- K2: block0 = exclusive scan, block1 = M = wh@wv ----------------
__global__ void k_scan_mw(const float* __restrict__ wh, const float* __restrict__ wv) {
    if (blockIdx.x == 1) {
        for (int t = threadIdx.x; t < 68 * 32; t += 1024) {
            int c = t >> 5, o = t & 31;
            float s = 0.f;
#pragma unroll 4
            for (int h = 0; h < 68; h++) s = fmaf(wh[c * 68 + h], wv[h * 32 + o], s);
            g_M[t] = s;
        }
        return;
    }
    __shared__ int sm[1024];
    int t = threadIdx.x;
    int base = t * 10;
    int loc[10];
    int s = 0;
#pragma unroll
    for (int j = 0; j < 10; j++) {
        int idx = base + j;
        int v = (idx < Nn) ? g_cnt[idx] : 0;
        loc[j] = v; s += v;
    }
    sm[t] = s;
    __syncthreads();
    for (int o = 1; o < 1024; o <<= 1) {
        int v = (t >= o) ? sm[t - o] : 0;
        __syncthreads();
        sm[t] += v;
        __syncthreads();
    }
    int run = sm[t] - s;
#pragma unroll
    for (int j = 0; j < 10; j++) {
        int idx = base + j;
        if (idx < Nn) { g_off[idx] = run; g_cur[idx] = run; run += loc[j]; }
    }
    if (t == 1023) g_off[Nn] = sm[1023];
}

// ---------------- K3: scatter edge ids ----------------
__global__ void k_scatter(const int* __restrict__ ei) {
    int e = blockIdx.x * blockDim.x + threadIdx.x;
    if (e < Ee) {
        int d = ei[Ee + e];
        int pos = atomicAdd(&g_cur[d], 1);
        g_order[pos] = e;
    }
}

// ---------------- K4: per-node vector projections, f32x2 node-pairs, 16 nodes/block ----------------
__global__ void __launch_bounds__(224)
k_nvh(const float* __restrict__ node_v, const float* __restrict__ wh) {
    __shared__ float swh[68 * 68];               // 18.5 KB
    __shared__ __align__(8) float svp[3 * 512];  // [d][c][q], q contiguous (16), 6 KB
    int t = threadIdx.x;                         // 224 threads
    int n0 = blockIdx.x * 16;
    for (int i = t; i < 68 * 68; i += 224) swh[i] = wh[i];
    for (int i = t; i < 16 * 96; i += 224) {
        int q = i / 96, c96 = i - q * 96;        // c96 = c*3 + d
        int c = c96 / 3, d = c96 - c * 3;
        svp[d * 512 + c * 16 + q] = node_v[(size_t)(n0 + q) * 96 + c96];
    }
    __syncthreads();
    if (t < 204) {
        int d = t / 68, h = t - d * 68;
        int ps = perm68(h);
        const float* sv = &svp[d * 512];
        u64 fs[8], fd[8];
#pragma unroll
        for (int p = 0; p < 8; p++) { fs[p] = 0; fd[p] = 0; }
#pragma unroll 4
        for (int c = 0; c < 32; c++) {
            float ws = swh[c * 68 + h], wd = swh[(36 + c) * 68 + h];
            u64 ws2 = pk2(ws, ws), wd2 = pk2(wd, wd);
#pragma unroll
            for (int p = 0; p < 8; p++) {
                u64 a = *(const u64*)(sv + c * 16 + 2 * p);   // node pair (2p, 2p+1)
                fs[p] = fma2(a, ws2, fs[p]);
                fd[p] = fma2(a, wd2, fd[p]);
            }
        }
#pragma unroll
        for (int p = 0; p < 8; p++) {
            float s0, s1, d0, d1;
            upk2(fs[p], s0, s1);
            upk2(fd[p], d0, d1);
            size_t b0 = (size_t)(n0 + 2 * p) * 408;
            size_t b1 = (size_t)(n0 + 2 * p + 1) * 408;
            g_nvh[b0 + d * 68 + ps] = s0;
            g_nvh[b1 + d * 68 + ps] = s1;
            g_nvh[b0 + (3 + d) * 68 + ps] = d0;
            g_nvh[b1 + (3 + d) * 68 + ps] = d1;
        }
    }
}

// ---------------- K6: per-node aggregation, one warp per node, 1-deep lookahead ----------------
__global__ void k_agg(const float* __restrict__ node_s, const float* __restrict__ node_v,
                      const float* __restrict__ edge_s, const float* __restrict__ edge_v,
                      const float* __restrict__ wh, const int* __restrict__ ei) {
    int warp = (blockIdx.x * blockDim.x + threadIdx.x) >> 5;
    int lane = threadIdx.x & 31;
    if (warp >= Nn) return;
    int n = warp;
    bool l24 = (lane < 24), l12 = (lane < 12);
    int h0 = lane, h1 = lane + 32;
    int lcl = (lane < 4) ? lane : 0;       // clamped k2 lane
    int h2s = 64 + lcl;                    // permuted slot for k2 channels
    bool h2v = (lane < 4);

    // per-node constants: k0,k1 packed via LDG.64 on permuted rows, k2 scalar
    u64 nd01[3], we01[4];
    float nd2[3], we2[4];
#pragma unroll
    for (int d = 0; d < 3; d++) {
        const float* p = g_nvh + (size_t)n * 408 + (3 + d) * 68;
        nd01[d] = *(const u64*)(p + 2 * lane);
        nd2[d]  = p[h2s];
    }
#pragma unroll
    for (int c = 0; c < 4; c++) {
        const float* p = wh + (32 + c) * 68;
        we01[c] = pk2(p[h0], p[h1]);
        we2[c]  = p[64 + lcl];
    }

    u64 aS0 = 0, aS1 = 0, aS2 = 0, aS3 = 0;
    u64 aE = 0;
    u64 aV0 = 0, aV1 = 0;
    float aEV = 0.f;
    u64 aN01 = 0;
    float aN2 = 0.f;

    int p0 = g_off[n], p1 = g_off[n + 1];
    int m = p1 - p0;
    if (m > 0) {
        int e = g_order[p0];
        int s = ei[e];
        for (int p = p0; p < p1; p++) {
            int e_nx = e, s_nx = s;
            if (p + 1 < p1) { e_nx = g_order[p + 1]; s_nx = ei[e_nx]; }

            {
                const ulonglong2* a = (const ulonglong2*)(node_s + (size_t)s * 256 + 4 * lane);
                const ulonglong2* b = (const ulonglong2*)(node_s + (size_t)s * 256 + 128 + 4 * lane);
                ulonglong2 x = *a, y = *b;
                aS0 = add2(aS0, x.x); aS1 = add2(aS1, x.y);
                aS2 = add2(aS2, y.x); aS3 = add2(aS3, y.y);
            }
            aE = add2(aE, *(const u64*)(edge_s + (size_t)e * 64 + 2 * lane));
            if (l24) {
                ulonglong2 v = *(const ulonglong2*)(node_v + (size_t)s * 96 + 4 * lane);
                aV0 = add2(aV0, v.x); aV1 = add2(aV1, v.y);
            }
            if (l12) aEV += edge_v[(size_t)e * 12 + lane];

            // edge_v broadcast: [c][d] layout, 12 floats
            const float4* evp = (const float4*)(edge_v + (size_t)e * 12);
            float4 q0 = evp[0], q1 = evp[1], q2 = evp[2];

            const float* nh = g_nvh + (size_t)s * 408;
            u64 ssq01 = 0;
            float ssq2 = 0.f;
#pragma unroll
            for (int d = 0; d < 3; d++) {
                u64 nv2 = *(const u64*)(nh + d * 68 + 2 * lane);
                float nc = nh[d * 68 + h2s];
                u64 v2 = add2(nv2, nd01[d]);
                float vs = nc + nd2[d];
                float c0 = (d == 0) ? q0.x : (d == 1) ? q0.y : q0.z;
                float c1 = (d == 0) ? q0.w : (d == 1) ? q1.x : q1.y;
                float c2 = (d == 0) ? q1.z : (d == 1) ? q1.w : q2.x;
                float c3 = (d == 0) ? q2.y : (d == 1) ? q2.z : q2.w;
                v2 = fma2(pk2(c0, c0), we01[0], v2);
                v2 = fma2(pk2(c1, c1), we01[1], v2);
                v2 = fma2(pk2(c2, c2), we01[2], v2);
                v2 = fma2(pk2(c3, c3), we01[3], v2);
                vs = fmaf(c0, we2[0], vs);
                vs = fmaf(c1, we2[1], vs);
                vs = fmaf(c2, we2[2], vs);
                vs = fmaf(c3, we2[3], vs);
                ssq01 = fma2(v2, v2, ssq01);
                ssq2 = fmaf(vs, vs, ssq2);
            }
            float s0, s1;
            upk2(ssq01, s0, s1);
            aN01 = add2(aN01, pk2(sqrt_apx(fmaxf(s0, 1e-8f)), sqrt_apx(fmaxf(s1, 1e-8f))));
            aN2 += sqrt_apx(fmaxf(ssq2, 1e-8f));

            e = e_nx; s = s_nx;
        }
    }

    // ---- write full GEMM X row ----
    float cnt = (float)m;
    float* ag = g_agg + (size_t)n * KPAD;
    *(ulonglong2*)(ag + 4 * lane)       = make_ulonglong2(aS0, aS1);
    *(ulonglong2*)(ag + 128 + 4 * lane) = make_ulonglong2(aS2, aS3);
    *(u64*)(ag + 256 + 2 * lane) = aE;
    {   // cnt * node_s[n]
        float4 a = *(const float4*)(node_s + (size_t)n * 256 + 4 * lane);
        float4 b = *(const float4*)(node_s + (size_t)n * 256 + 128 + 4 * lane);
        a.x *= cnt; a.y *= cnt; a.z *= cnt; a.w *= cnt;
        b.x *= cnt; b.y *= cnt; b.z *= cnt; b.w *= cnt;
        *(float4*)(ag + 320 + 4 * lane) = a;
        *(float4*)(ag + 448 + 4 * lane) = b;
    }
    {
        float n0v, n1v;
        upk2(aN01, n0v, n1v);
        ag[576 + lane] = n0v; ag[608 + lane] = n1v;
    }
    if (h2v) ag[640 + lane] = aN2;
    if (lane >= 4 && lane < 16) ag[640 + lane] = 0.f;   // pad [644,656)

    float* vg = g_vagg + (size_t)n * 112;
    if (l24) *(ulonglong2*)(vg + 4 * lane) = make_ulonglong2(aV0, aV1);
    if (l12) vg[96 + lane] = aEV;

    if (lane == 0) g_cnt[n] = 0;          // reset histogram for next replay
}

// ---------------- K7: node GEMM, double-buffered, FFMA2, 139 balanced blocks ----------------
__global__ void __launch_bounds__(256, 1)
k_gemm(const float* __restrict__ ws_w, const float* __restrict__ ws_b,
       float* __restrict__ out) {
    __shared__ float Xs[2][16][72];
    __shared__ float Ws[2][16][256];
    __shared__ float sCnt[72];
    int tid = threadIdx.x;
    int r0 = blockIdx.x * 72;
    int tc = tid & 63;
    int rg = tid >> 6;

    if (tid < 72) {
        int r = r0 + tid;
        sCnt[tid] = (r < Nn) ? (float)(g_off[r + 1] - g_off[r]) : 0.f;
    }

    int rowA = tid >> 2, kqA = tid & 3;
    int rA = r0 + rowA;
    int rowB = (tid + 256) >> 2, kqB = tid & 3;
    int rB = r0 + rowB;

    float4 x0, x1, w[4];
    const float4 z4 = make_float4(0.f, 0.f, 0.f, 0.f);

    auto loadTiles = [&](int kt) {
        int k0 = kt * 16;
        x0 = (rA < Nn) ? *(const float4*)(g_agg + (size_t)rA * KPAD + k0 + kqA * 4) : z4;
        if (tid < 32)
            x1 = (rB < Nn) ? *(const float4*)(g_agg + (size_t)rB * KPAD + k0 + kqB * 4) : z4;
#pragma unroll
        for (int q = 0; q < 4; q++) {
            int f = tid + 256 * q;
            int kk = f >> 6, c4 = (f & 63) * 4;
            int k = k0 + kk;
            w[q] = (k < KTOT) ? *(const float4*)(ws_w + (size_t)k * 256 + c4) : z4;
        }
    };
    auto stsTiles = [&](int b) {
        Xs[b][kqA * 4 + 0][rowA] = x0.x;
        Xs[b][kqA * 4 + 1][rowA] = x0.y;
        Xs[b][kqA * 4 + 2][rowA] = x0.z;
        Xs[b][kqA * 4 + 3][rowA] = x0.w;
        if (tid < 32) {
            Xs[b][kqB * 4 + 0][rowB] = x1.x;
            Xs[b][kqB * 4 + 1][rowB] = x1.y;
            Xs[b][kqB * 4 + 2][rowB] = x1.z;
            Xs[b][kqB * 4 + 3][rowB] = x1.w;
        }
#pragma unroll
        for (int q = 0; q < 4; q++) {
            int f = tid + 256 * q;
            int kk = f >> 6, c4 = (f & 63) * 4;
            *(float4*)(&Ws[b][kk][c4]) = w[q];
        }
    };

    u64 acc[9][4];
#pragma unroll
    for (int p = 0; p < 9; p++)
#pragma unroll
        for (int c = 0; c < 4; c++) acc[p][c] = 0;

    loadTiles(0);
    stsTiles(0);
    __syncthreads();

    for (int kt = 0; kt < 41; kt++) {
        int cur = kt & 1;
        if (kt < 40) loadTiles(kt + 1);
#pragma unroll
        for (int kk = 0; kk < 16; kk++) {
            float4 b4 = *(const float4*)(&Ws[cur][kk][tc * 4]);
            u64 b0 = pk2(b4.x, b4.x), b1 = pk2(b4.y, b4.y);
            u64 b2 = pk2(b4.z, b4.z), b3 = pk2(b4.w, b4.w);
#pragma unroll
            for (int p = 0; p < 9; p++) {
                u64 av = *(const u64*)(&Xs[cur][kk][rg * 18 + 2 * p]);
                acc[p][0] = fma2(av, b0, acc[p][0]);
                acc[p][1] = fma2(av, b1, acc[p][1]);
                acc[p][2] = fma2(av, b2, acc[p][2]);
                acc[p][3] = fma2(av, b3, acc[p][3]);
            }
        }
        if (kt < 40) stsTiles(cur ^ 1);
        __syncthreads();
    }

    float4 bias = *(const float4*)(ws_b + tc * 4);
#pragma unroll
    for (int p = 0; p < 9; p++) {
        int row = rg * 18 + 2 * p;
        float lo[4], hi[4];
#pragma unroll
        for (int c = 0; c < 4; c++) upk2(acc[p][c], lo[c], hi[c]);
#pragma unroll
        for (int h = 0; h < 2; h++) {
            int r = r0 + row + h;
            if (r >= Nn) continue;
            float cnt = sCnt[row + h];
            float sc = 1.f / fmaxf(cnt, 1.f);
            float bc = (cnt > 0.f) ? 1.f : 0.f;
            const float* v = h ? hi : lo;
            float4 o;
            o.x = v[0] * sc + bias.x * bc;
            o.y = v[1] * sc + bias.y * bc;
            o.z = v[2] * sc + bias.z * bc;
            o.w = v[3] * sc + bias.w * bc;
            *(float4*)(out + (size_t)r * OUTC + tc * 4) = o;
        }
    }
}

// ---------------- K8: vector output ----------------
__global__ void k_vec(const float* __restrict__ node_v, float* __restrict__ out) {
    __shared__ float Msm[68 * 32];
    __shared__ float vag[204];
    int t = threadIdx.x;                   // 96 threads
    for (int i = t; i < 68 * 32; i += 96) Msm[i] = g_M[i];
#pragma unroll 1
    for (int q = 0; q < 8; q++) {
        int n = blockIdx.x * 8 + q;        // grid = 1250
        float cf = (float)(g_off[n + 1] - g_off[n]);
        __syncthreads();
        vag[t] = g_vagg[(size_t)n * 112 + t];
        if (t < 12) vag[96 + t] = g_vagg[(size_t)n * 112 + 96 + t];
        vag[108 + t] = cf * node_v[(size_t)n * 96 + t];
        __syncthreads();
        int o = t / 3, d = t % 3;
        float s = 0.f;
#pragma unroll 4
        for (int c = 0; c < 68; c++) s = fmaf(vag[c * 3 + d], Msm[c * 32 + o], s);
        out[(size_t)n * OUTC + 256 + o * 3 + d] = s / fmaxf(cf, 1.f);
    }
}

// ---------------- launch: forked-capture overlap (nvh || sort chain; vec || gemm) ----------------
extern "C" void kernel_launch(void* const* d_in, const int* in_sizes, int n_in,
                              void* d_out, int out_size) {
    const float* node_s = (const float*)d_in[0];
    const float* node_v = (const float*)d_in[1];
    const float* edge_s = (const float*)d_in[2];
    const float* edge_v = (const float*)d_in[3];
    const float* wh     = (const float*)d_in[4];
    const float* ws_w   = (const float*)d_in[5];
    const float* ws_b   = (const float*)d_in[6];
    const float* wv     = (const float*)d_in[7];
    const int*   ei     = (const int*)d_in[8];
    float* out = (float*)d_out;

    cudaStream_t s1;
    cudaStreamCreateWithFlags(&s1, cudaStreamNonBlocking);
    cudaEvent_t evFork, evNvh, evAgg, evVec;
    cudaEventCreateWithFlags(&evFork, cudaEventDisableTiming);
    cudaEventCreateWithFlags(&evNvh,  cudaEventDisableTiming);
    cudaEventCreateWithFlags(&evAgg,  cudaEventDisableTiming);
    cudaEventCreateWithFlags(&evVec,  cudaEventDisableTiming);

    // fork: k_nvh runs concurrently with the hist->scan->scatter chain
    cudaEventRecord(evFork, 0);
    cudaStreamWaitEvent(s1, evFork, 0);
    k_nvh<<<Nn / 16, 224, 0, s1>>>(node_v, wh);
    cudaEventRecord(evNvh, s1);

    k_hist<<<(Ee + 255) / 256, 256>>>(ei);
    k_scan_mw<<<2, 1024>>>(wh, wv);
    k_scatter<<<(Ee + 255) / 256, 256>>>(ei);

    // join: k_agg needs both branches
    cudaStreamWaitEvent(0, evNvh, 0);
    k_agg<<<(Nn + 7) / 8, 256>>>(node_s, node_v, edge_s, edge_v, wh, ei);

    // fork: k_vec (disjoint out columns) runs alongside k_gemm
    cudaEventRecord(evAgg, 0);
    cudaStreamWaitEvent(s1, evAgg, 0);
    k_vec<<<Nn / 8, 96, 0, s1>>>(node_v, out);
    cudaEventRecord(evVec, s1);

    k_gemm<<<139, 256>>>(ws_w, ws_b, out);
    cudaStreamWaitEvent(0, evVec, 0);   // join so the graph's end covers k_vec

    cudaEventDestroy(evFork);
    cudaEventDestroy(evNvh);
    cudaEventDestroy(evAgg);
    cudaEventDestroy(evVec);
    cudaStreamDestroy(s1);
}

// round 17
// speedup vs baseline: 1.1580x; 1.0664x over previous
#include <cuda_runtime.h>
#include <math.h>

#define Nn 10000
#define Ee 320000
#define KTOT 644     // 576 scalar cat + 68 vn
#define KPAD 656     // 41 * 16
#define OUTC 352     // 256 scalar + 96 vector

typedef unsigned long long u64;

// ---------------- f32x2 / misc helpers ----------------
__device__ __forceinline__ u64 pk2(float x, float y) {
    u64 r; asm("mov.b64 %0,{%1,%2};" : "=l"(r) : "f"(x), "f"(y)); return r;
}
__device__ __forceinline__ void upk2(u64 v, float& x, float& y) {
    asm("mov.b64 {%0,%1},%2;" : "=f"(x), "=f"(y) : "l"(v));
}
__device__ __forceinline__ u64 fma2(u64 a, u64 b, u64 c) {
    u64 r; asm("fma.rn.f32x2 %0,%1,%2,%3;" : "=l"(r) : "l"(a), "l"(b), "l"(c)); return r;
}
__device__ __forceinline__ u64 add2(u64 a, u64 b) {
    u64 r; asm("add.rn.f32x2 %0,%1,%2;" : "=l"(r) : "l"(a), "l"(b)); return r;
}
__device__ __forceinline__ float sqrt_apx(float x) {
    float r; asm("sqrt.approx.f32 %0,%1;" : "=f"(r) : "f"(x)); return r;
}
// channel -> permuted slot within a 68-float nvh row: pairs (h, h+32) adjacent
__device__ __forceinline__ int perm68(int h) {
    return h < 32 ? 2 * h : (h < 64 ? 2 * (h - 32) + 1 : h);
}

// ---------------- scratch (zero-initialized at module load) ----------------
__device__ int   g_cnt[Nn];
__device__ int   g_off[Nn + 1];
__device__ int   g_cur[Nn];
__device__ int   g_order[Ee];
__device__ float g_nvh[(size_t)Nn * 408];   // [n][j][68-permuted], j=0..2 src-d, 3..5 dst-d
__device__ float g_agg[(size_t)Nn * KPAD];  // GEMM X row
__device__ float g_vagg[(size_t)Nn * 112];  // [0,96) Σv_src | [96,108) Σe_v
__device__ float g_M[68 * 32];              // wh @ wv

// ---------------- K1: histogram of dst (g_cnt zeroed by k_agg at end of each run) ----------------
__global__ void k_hist(const int* __restrict__ ei) {
    int e = blockIdx.x * blockDim.x + threadIdx.x;
    if (e < Ee) atomicAdd(&g_cnt[ei[Ee + e]], 1);
}

// ---------------- K2: block0 = exclusive scan, block1 = M = wh@wv ----------------
__global__ void k_scan_mw(const float* __restrict__ wh, const float* __restrict__ wv) {
    if (blockIdx.x == 1) {
        for (int t = threadIdx.x; t < 68 * 32; t += 1024) {
            int c = t >> 5, o = t & 31;
            float s = 0.f;
#pragma unroll 4
            for (int h = 0; h < 68; h++) s = fmaf(wh[c * 68 + h], wv[h * 32 + o], s);
            g_M[t] = s;
        }
        return;
    }
    __shared__ int sm[1024];
    int t = threadIdx.x;
    int base = t * 10;
    int loc[10];
    int s = 0;
#pragma unroll
    for (int j = 0; j < 10; j++) {
        int idx = base + j;
        int v = (idx < Nn) ? g_cnt[idx] : 0;
        loc[j] = v; s += v;
    }
    sm[t] = s;
    __syncthreads();
    for (int o = 1; o < 1024; o <<= 1) {
        int v = (t >= o) ? sm[t - o] : 0;
        __syncthreads();
        sm[t] += v;
        __syncthreads();
    }
    int run = sm[t] - s;
#pragma unroll
    for (int j = 0; j < 10; j++) {
        int idx = base + j;
        if (idx < Nn) { g_off[idx] = run; g_cur[idx] = run; run += loc[j]; }
    }
    if (t == 1023) g_off[Nn] = sm[1023];
}

// ---------------- K3: scatter edge ids ----------------
__global__ void k_scatter(const int* __restrict__ ei) {
    int e = blockIdx.x * blockDim.x + threadIdx.x;
    if (e < Ee) {
        int d = ei[Ee + e];
        int pos = atomicAdd(&g_cur[d], 1);
        g_order[pos] = e;
    }
}

// ---------------- K4: per-node vector projections, f32x2 node-pairs, 16 nodes/block ----------------
__global__ void __launch_bounds__(224)
k_nvh(const float* __restrict__ node_v, const float* __restrict__ wh) {
    __shared__ float swh[68 * 68];               // 18.5 KB
    __shared__ __align__(8) float svp[3 * 512];  // [d][c][q], q contiguous (16), 6 KB
    int t = threadIdx.x;                         // 224 threads
    int n0 = blockIdx.x * 16;
    for (int i = t; i < 68 * 68; i += 224) swh[i] = wh[i];
    for (int i = t; i < 16 * 96; i += 224) {
        int q = i / 96, c96 = i - q * 96;        // c96 = c*3 + d
        int c = c96 / 3, d = c96 - c * 3;
        svp[d * 512 + c * 16 + q] = node_v[(size_t)(n0 + q) * 96 + c96];
    }
    __syncthreads();
    if (t < 204) {
        int d = t / 68, h = t - d * 68;
        int ps = perm68(h);
        const float* sv = &svp[d * 512];
        u64 fs[8], fd[8];
#pragma unroll
        for (int p = 0; p < 8; p++) { fs[p] = 0; fd[p] = 0; }
#pragma unroll 4
        for (int c = 0; c < 32; c++) {
            float ws = swh[c * 68 + h], wd = swh[(36 + c) * 68 + h];
            u64 ws2 = pk2(ws, ws), wd2 = pk2(wd, wd);
#pragma unroll
            for (int p = 0; p < 8; p++) {
                u64 a = *(const u64*)(sv + c * 16 + 2 * p);   // node pair (2p, 2p+1)
                fs[p] = fma2(a, ws2, fs[p]);
                fd[p] = fma2(a, wd2, fd[p]);
            }
        }
#pragma unroll
        for (int p = 0; p < 8; p++) {
            float s0, s1, d0, d1;
            upk2(fs[p], s0, s1);
            upk2(fd[p], d0, d1);
            size_t b0 = (size_t)(n0 + 2 * p) * 408;
            size_t b1 = (size_t)(n0 + 2 * p + 1) * 408;
            g_nvh[b0 + d * 68 + ps] = s0;
            g_nvh[b1 + d * 68 + ps] = s1;
            g_nvh[b0 + (3 + d) * 68 + ps] = d0;
            g_nvh[b1 + (3 + d) * 68 + ps] = d1;
        }
    }
}

// ---------------- K6: per-node aggregation, one warp per node, 1-deep lookahead ----------------
__global__ void k_agg(const float* __restrict__ node_s, const float* __restrict__ node_v,
                      const float* __restrict__ edge_s, const float* __restrict__ edge_v,
                      const float* __restrict__ wh, const int* __restrict__ ei) {
    int warp = (blockIdx.x * blockDim.x + threadIdx.x) >> 5;
    int lane = threadIdx.x & 31;
    if (warp >= Nn) return;
    int n = warp;
    bool l24 = (lane < 24), l12 = (lane < 12);
    int h0 = lane, h1 = lane + 32;
    int lcl = (lane < 4) ? lane : 0;       // clamped k2 lane
    int h2s = 64 + lcl;                    // permuted slot for k2 channels
    bool h2v = (lane < 4);

    // per-node constants: k0,k1 packed via LDG.64 on permuted rows, k2 scalar
    u64 nd01[3], we01[4];
    float nd2[3], we2[4];
#pragma unroll
    for (int d = 0; d < 3; d++) {
        const float* p = g_nvh + (size_t)n * 408 + (3 + d) * 68;
        nd01[d] = *(const u64*)(p + 2 * lane);
        nd2[d]  = p[h2s];
    }
#pragma unroll
    for (int c = 0; c < 4; c++) {
        const float* p = wh + (32 + c) * 68;
        we01[c] = pk2(p[h0], p[h1]);
        we2[c]  = p[64 + lcl];
    }

    u64 aS0 = 0, aS1 = 0, aS2 = 0, aS3 = 0;
    u64 aE = 0;
    u64 aV0 = 0, aV1 = 0;
    float aEV = 0.f;
    u64 aN01 = 0;
    float aN2 = 0.f;

    int p0 = g_off[n], p1 = g_off[n + 1];
    int m = p1 - p0;
    if (m > 0) {
        int e = g_order[p0];
        int s = ei[e];
        for (int p = p0; p < p1; p++) {
            int e_nx = e, s_nx = s;
            if (p + 1 < p1) { e_nx = g_order[p + 1]; s_nx = ei[e_nx]; }

            {
                const ulonglong2* a = (const ulonglong2*)(node_s + (size_t)s * 256 + 4 * lane);
                const ulonglong2* b = (const ulonglong2*)(node_s + (size_t)s * 256 + 128 + 4 * lane);
                ulonglong2 x = *a, y = *b;
                aS0 = add2(aS0, x.x); aS1 = add2(aS1, x.y);
                aS2 = add2(aS2, y.x); aS3 = add2(aS3, y.y);
            }
            aE = add2(aE, *(const u64*)(edge_s + (size_t)e * 64 + 2 * lane));
            if (l24) {
                ulonglong2 v = *(const ulonglong2*)(node_v + (size_t)s * 96 + 4 * lane);
                aV0 = add2(aV0, v.x); aV1 = add2(aV1, v.y);
            }
            if (l12) aEV += edge_v[(size_t)e * 12 + lane];

            // edge_v broadcast: [c][d] layout, 12 floats
            const float4* evp = (const float4*)(edge_v + (size_t)e * 12);
            float4 q0 = evp[0], q1 = evp[1], q2 = evp[2];

            const float* nh = g_nvh + (size_t)s * 408;
            u64 ssq01 = 0;
            float ssq2 = 0.f;
#pragma unroll
            for (int d = 0; d < 3; d++) {
                u64 nv2 = *(const u64*)(nh + d * 68 + 2 * lane);
                float nc = nh[d * 68 + h2s];
                u64 v2 = add2(nv2, nd01[d]);
                float vs = nc + nd2[d];
                float c0 = (d == 0) ? q0.x : (d == 1) ? q0.y : q0.z;
                float c1 = (d == 0) ? q0.w : (d == 1) ? q1.x : q1.y;
                float c2 = (d == 0) ? q1.z : (d == 1) ? q1.w : q2.x;
                float c3 = (d == 0) ? q2.y : (d == 1) ? q2.z : q2.w;
                v2 = fma2(pk2(c0, c0), we01[0], v2);
                v2 = fma2(pk2(c1, c1), we01[1], v2);
                v2 = fma2(pk2(c2, c2), we01[2], v2);
                v2 = fma2(pk2(c3, c3), we01[3], v2);
                vs = fmaf(c0, we2[0], vs);
                vs = fmaf(c1, we2[1], vs);
                vs = fmaf(c2, we2[2], vs);
                vs = fmaf(c3, we2[3], vs);
                ssq01 = fma2(v2, v2, ssq01);
                ssq2 = fmaf(vs, vs, ssq2);
            }
            float s0, s1;
            upk2(ssq01, s0, s1);
            aN01 = add2(aN01, pk2(sqrt_apx(fmaxf(s0, 1e-8f)), sqrt_apx(fmaxf(s1, 1e-8f))));
            aN2 += sqrt_apx(fmaxf(ssq2, 1e-8f));

            e = e_nx; s = s_nx;
        }
    }

    // ---- write full GEMM X row ----
    float cnt = (float)m;
    float* ag = g_agg + (size_t)n * KPAD;
    *(ulonglong2*)(ag + 4 * lane)       = make_ulonglong2(aS0, aS1);
    *(ulonglong2*)(ag + 128 + 4 * lane) = make_ulonglong2(aS2, aS3);
    *(u64*)(ag + 256 + 2 * lane) = aE;
    {   // cnt * node_s[n]
        float4 a = *(const float4*)(node_s + (size_t)n * 256 + 4 * lane);
        float4 b = *(const float4*)(node_s + (size_t)n * 256 + 128 + 4 * lane);
        a.x *= cnt; a.y *= cnt; a.z *= cnt; a.w *= cnt;
        b.x *= cnt; b.y *= cnt; b.z *= cnt; b.w *= cnt;
        *(float4*)(ag + 320 + 4 * lane) = a;
        *(float4*)(ag + 448 + 4 * lane) = b;
    }
    {
        float n0v, n1v;
        upk2(aN01, n0v, n1v);
        ag[576 + lane] = n0v; ag[608 + lane] = n1v;
    }
    if (h2v) ag[640 + lane] = aN2;
    if (lane >= 4 && lane < 16) ag[640 + lane] = 0.f;   // pad [644,656)

    float* vg = g_vagg + (size_t)n * 112;
    if (l24) *(ulonglong2*)(vg + 4 * lane) = make_ulonglong2(aV0, aV1);
    if (l12) vg[96 + lane] = aEV;

    if (lane == 0) g_cnt[n] = 0;          // reset histogram for next replay
}

// ---------------- K7: node GEMM, double-buffered, FFMA2, 139 balanced blocks ----------------
__global__ void __launch_bounds__(256, 1)
k_gemm(const float* __restrict__ ws_w, const float* __restrict__ ws_b,
       float* __restrict__ out) {
    __shared__ float Xs[2][16][72];
    __shared__ float Ws[2][16][256];
    __shared__ float sCnt[72];
    int tid = threadIdx.x;
    int r0 = blockIdx.x * 72;
    int tc = tid & 63;
    int rg = tid >> 6;

    if (tid < 72) {
        int r = r0 + tid;
        sCnt[tid] = (r < Nn) ? (float)(g_off[r + 1] - g_off[r]) : 0.f;
    }

    int rowA = tid >> 2, kqA = tid & 3;
    int rA = r0 + rowA;
    int rowB = (tid + 256) >> 2, kqB = tid & 3;
    int rB = r0 + rowB;

    float4 x0, x1, w[4];
    const float4 z4 = make_float4(0.f, 0.f, 0.f, 0.f);

    auto loadTiles = [&](int kt) {
        int k0 = kt * 16;
        x0 = (rA < Nn) ? *(const float4*)(g_agg + (size_t)rA * KPAD + k0 + kqA * 4) : z4;
        if (tid < 32)
            x1 = (rB < Nn) ? *(const float4*)(g_agg + (size_t)rB * KPAD + k0 + kqB * 4) : z4;
#pragma unroll
        for (int q = 0; q < 4; q++) {
            int f = tid + 256 * q;
            int kk = f >> 6, c4 = (f & 63) * 4;
            int k = k0 + kk;
            w[q] = (k < KTOT) ? *(const float4*)(ws_w + (size_t)k * 256 + c4) : z4;
        }
    };
    auto stsTiles = [&](int b) {
        Xs[b][kqA * 4 + 0][rowA] = x0.x;
        Xs[b][kqA * 4 + 1][rowA] = x0.y;
        Xs[b][kqA * 4 + 2][rowA] = x0.z;
        Xs[b][kqA * 4 + 3][rowA] = x0.w;
        if (tid < 32) {
            Xs[b][kqB * 4 + 0][rowB] = x1.x;
            Xs[b][kqB * 4 + 1][rowB] = x1.y;
            Xs[b][kqB * 4 + 2][rowB] = x1.z;
            Xs[b][kqB * 4 + 3][rowB] = x1.w;
        }
#pragma unroll
        for (int q = 0; q < 4; q++) {
            int f = tid + 256 * q;
            int kk = f >> 6, c4 = (f & 63) * 4;
            *(float4*)(&Ws[b][kk][c4]) = w[q];
        }
    };

    u64 acc[9][4];
#pragma unroll
    for (int p = 0; p < 9; p++)
#pragma unroll
        for (int c = 0; c < 4; c++) acc[p][c] = 0;

    loadTiles(0);
    stsTiles(0);
    __syncthreads();

    for (int kt = 0; kt < 41; kt++) {
        int cur = kt & 1;
        if (kt < 40) loadTiles(kt + 1);
#pragma unroll
        for (int kk = 0; kk < 16; kk++) {
            float4 b4 = *(const float4*)(&Ws[cur][kk][tc * 4]);
            u64 b0 = pk2(b4.x, b4.x), b1 = pk2(b4.y, b4.y);
            u64 b2 = pk2(b4.z, b4.z), b3 = pk2(b4.w, b4.w);
#pragma unroll
            for (int p = 0; p < 9; p++) {
                u64 av = *(const u64*)(&Xs[cur][kk][rg * 18 + 2 * p]);
                acc[p][0] = fma2(av, b0, acc[p][0]);
                acc[p][1] = fma2(av, b1, acc[p][1]);
                acc[p][2] = fma2(av, b2, acc[p][2]);
                acc[p][3] = fma2(av, b3, acc[p][3]);
            }
        }
        if (kt < 40) stsTiles(cur ^ 1);
        __syncthreads();
    }

    float4 bias = *(const float4*)(ws_b + tc * 4);
#pragma unroll
    for (int p = 0; p < 9; p++) {
        int row = rg * 18 + 2 * p;
        float lo[4], hi[4];
#pragma unroll
        for (int c = 0; c < 4; c++) upk2(acc[p][c], lo[c], hi[c]);
#pragma unroll
        for (int h = 0; h < 2; h++) {
            int r = r0 + row + h;
            if (r >= Nn) continue;
            float cnt = sCnt[row + h];
            float sc = 1.f / fmaxf(cnt, 1.f);
            float bc = (cnt > 0.f) ? 1.f : 0.f;
            const float* v = h ? hi : lo;
            float4 o;
            o.x = v[0] * sc + bias.x * bc;
            o.y = v[1] * sc + bias.y * bc;
            o.z = v[2] * sc + bias.z * bc;
            o.w = v[3] * sc + bias.w * bc;
            *(float4*)(out + (size_t)r * OUTC + tc * 4) = o;
        }
    }
}

// ---------------- K8: vector output ----------------
__global__ void k_vec(const float* __restrict__ node_v, float* __restrict__ out) {
    __shared__ float Msm[68 * 32];
    __shared__ float vag[204];
    int t = threadIdx.x;                   // 96 threads
    for (int i = t; i < 68 * 32; i += 96) Msm[i] = g_M[i];
#pragma unroll 1
    for (int q = 0; q < 8; q++) {
        int n = blockIdx.x * 8 + q;        // grid = 1250
        float cf = (float)(g_off[n + 1] - g_off[n]);
        __syncthreads();
        vag[t] = g_vagg[(size_t)n * 112 + t];
        if (t < 12) vag[96 + t] = g_vagg[(size_t)n * 112 + 96 + t];
        vag[108 + t] = cf * node_v[(size_t)n * 96 + t];
        __syncthreads();
        int o = t / 3, d = t % 3;
        float s = 0.f;
#pragma unroll 4
        for (int c = 0; c < 68; c++) s = fmaf(vag[c * 3 + d], Msm[c * 32 + o], s);
        out[(size_t)n * OUTC + 256 + o * 3 + d] = s / fmaxf(cf, 1.f);
    }
}

// ---------------- launch: single fork (nvh || hist->scan->scatter), rest serial ----------------
extern "C" void kernel_launch(void* const* d_in, const int* in_sizes, int n_in,
                              void* d_out, int out_size) {
    const float* node_s = (const float*)d_in[0];
    const float* node_v = (const float*)d_in[1];
    const float* edge_s = (const float*)d_in[2];
    const float* edge_v = (const float*)d_in[3];
    const float* wh     = (const float*)d_in[4];
    const float* ws_w   = (const float*)d_in[5];
    const float* ws_b   = (const float*)d_in[6];
    const float* wv     = (const float*)d_in[7];
    const int*   ei     = (const int*)d_in[8];
    float* out = (float*)d_out;

    cudaStream_t s1;
    cudaStreamCreateWithFlags(&s1, cudaStreamNonBlocking);
    cudaEvent_t evFork, evNvh;
    cudaEventCreateWithFlags(&evFork, cudaEventDisableTiming);
    cudaEventCreateWithFlags(&evNvh,  cudaEventDisableTiming);

    // fork: k_nvh runs concurrently with the hist->scan->scatter chain
    cudaEventRecord(evFork, 0);
    cudaStreamWaitEvent(s1, evFork, 0);
    k_nvh<<<Nn / 16, 224, 0, s1>>>(node_v, wh);
    cudaEventRecord(evNvh, s1);

    k_hist<<<(Ee + 255) / 256, 256>>>(ei);
    k_scan_mw<<<2, 1024>>>(wh, wv);
    k_scatter<<<(Ee + 255) / 256, 256>>>(ei);

    // join: k_agg needs both branches
    cudaStreamWaitEvent(0, evNvh, 0);
    k_agg<<<(Nn + 7) / 8, 256>>>(node_s, node_v, edge_s, edge_v, wh, ei);
    k_gemm<<<139, 256>>>(ws_w, ws_b, out);
    k_vec<<<Nn / 8, 96>>>(node_v, out);

    cudaEventDestroy(evFork);
    cudaEventDestroy(evNvh);
    cudaStreamDestroy(s1);
}